// round 14
// baseline (speedup 1.0000x reference)
#include <cuda_runtime.h>
#include <cuda_bf16.h>
#include <math.h>
#include <stdint.h>

#define BS   16
#define CIN  256
#define COUT 256
#define HH   80
#define WW   80
#define HWSZ 6400
#define HID  16
#define KNUM 5

// padded spatial grid: 82x82 (1-halo), row stride 82
#define QROW 82
#define QP   6724
#define PADQ 128                 // slack rows either side (halo over/under-run)
#define QTOT (QP + 2 * PADQ)     // 6980
#define NTILE 256                // GEMM N per CTA
#define NT    26
#define MTILE 128                // GEMM M per CTA
#define SPAN  422                // NTILE + 2*83 halo rows per chunk
#define XROWB 144                // row pitch bytes (72 bf16), gmem AND smem

// smem layout (bytes)
#define SO_XH     0
#define SO_XL     60768                      // SPAN*144
#define SO_WH(bf) (121536 + (bf) * 18432)
#define SO_WL(bf) (158400 + (bf) * 18432)
#define SO_BAR    195264
#define SMEM_TOTAL 195392
#define W_STAGE_B  18432                     // 128*144
#define X_STAGE_B  60768                     // 422*144

// ---------------- scratch ----------------
__device__ float g_pooled[BS * CIN];         // raw sums (memset 0 each call)
__device__ float g_mix[BS * 9 * 9];
__device__ float g_cinatt[BS * CIN];
__device__ float g_outatt[BS * COUT];
__device__ float g_aggb[BS * COUT];

__device__ __align__(128) __nv_bfloat16 g_xh[(size_t)BS * 4 * QTOT * 72];
__device__ __align__(128) __nv_bfloat16 g_xl[(size_t)BS * 4 * QTOT * 72];
__device__ __align__(128) __nv_bfloat16 g_wh[(size_t)BS * 9 * 4 * COUT * 72];
__device__ __align__(128) __nv_bfloat16 g_wl[(size_t)BS * 9 * 4 * COUT * 72];

__constant__ int c_perm[KNUM][9] = {
    {0,1,2,3,4,5,6,7,8},
    {3,0,1,6,4,2,7,8,5},
    {6,3,0,7,4,1,8,5,2},
    {7,6,3,8,4,0,5,2,1},
    {8,7,6,5,4,3,2,1,0},
};

__device__ __forceinline__ float sigmoidf_(float z) { return 1.f / (1.f + expf(-z)); }

// ================= low-level helpers =================
__device__ __forceinline__ uint32_t smem_u32(const void* p)
{
    return (uint32_t)__cvta_generic_to_shared(p);
}
__device__ __forceinline__ uint32_t elect_one_pred()
{
    uint32_t pred;
    asm volatile("{\n\t.reg .pred p;\n\telect.sync _|p, 0xFFFFFFFF;\n\t"
                 "selp.b32 %0, 1, 0, p;\n\t}" : "=r"(pred));
    return pred;
}
#define MBARRIER_INIT(addr, cnt) \
    asm volatile("mbarrier.init.shared.b64 [%0], %1;" :: "r"(addr), "r"(cnt) : "memory")
#define MBARRIER_EXPECT_TX(addr, tx) \
    asm volatile("mbarrier.arrive.expect_tx.shared.b64 _, [%0], %1;" :: "r"(addr), "r"(tx) : "memory")
#define MBARRIER_ARRIVE(addr) \
    asm volatile("mbarrier.arrive.shared.b64 _, [%0];" :: "r"(addr) : "memory")
#define MBARRIER_WAIT_PARITY(addr, par) do {                                        \
    uint32_t _m = (addr), _p = (par);                                               \
    asm volatile("{\n\t.reg .pred P1;\n\t"                                          \
        "WL_%=:\n\t"                                                                \
        "mbarrier.try_wait.parity.acquire.cta.shared::cta.b64 P1, [%0], %1, 0x989680;\n\t" \
        "@P1 bra.uni WD_%=;\n\t"                                                    \
        "bra.uni WL_%=;\n\t"                                                        \
        "WD_%=:\n\t}" :: "r"(_m), "r"(_p) : "memory");                              \
} while (0)
#define BULK_G2S(dst, src, bytes, mbar)                                             \
    asm volatile("cp.async.bulk.shared::cta.global.mbarrier::complete_tx::bytes "   \
        "[%0], [%1], %2, [%3];"                                                     \
        :: "r"((uint32_t)(dst)), "l"(src), "r"((uint32_t)(bytes)),                  \
           "r"((uint32_t)(mbar)) : "memory")
#define FENCE_PROXY_ASYNC() asm volatile("fence.proxy.async.shared::cta;" ::: "memory")

#define LDSM4(r, addr)                                                        \
    asm volatile("ldmatrix.sync.aligned.m8n8.x4.shared.b16 {%0,%1,%2,%3}, [%4];" \
                 : "=r"((r)[0]), "=r"((r)[1]), "=r"((r)[2]), "=r"((r)[3])     \
                 : "r"(addr))

#define MMA(d, a, b0, b1)                                                     \
    asm volatile("mma.sync.aligned.m16n8k16.row.col.f32.bf16.bf16.f32 "      \
                 "{%0,%1,%2,%3}, {%4,%5,%6,%7}, {%8,%9}, {%0,%1,%2,%3};"     \
                 : "+f"((d)[0]), "+f"((d)[1]), "+f"((d)[2]), "+f"((d)[3])    \
                 : "r"((a)[0]), "r"((a)[1]), "r"((a)[2]), "r"((a)[3]),       \
                   "r"(b0), "r"(b1))

// ---------------- kernel 2: attention heads + mix + bias ----------------
__global__ void att_kernel(const float* __restrict__ w_net,
                           const float* __restrict__ w_nfc,
                           const float* __restrict__ w_cin,
                           const float* __restrict__ w_k2,
                           const float* __restrict__ w_out,
                           const float* __restrict__ b_base,
                           const float* __restrict__ b_extra)
{
    __shared__ float h_s[BS][HID];
    __shared__ float natt_s[BS][KNUM];
    __shared__ float k2_s[BS][9];
    int t = threadIdx.x;
    {
        int b = t >> 4, j = t & 15;
        const float* pr = &g_pooled[b * CIN];
        const float* wr = &w_net[j * CIN];
        float s = 0.f;
        for (int i = 0; i < CIN; ++i) s += pr[i] * wr[i];
        h_s[b][j] = fmaxf(s * (1.f / (float)HWSZ), 0.f);   // pooled holds raw sums
    }
    __syncthreads();
    if (t < BS) {
        float l[KNUM];
        float mx = -1e30f;
        for (int k = 0; k < KNUM; ++k) {
            float s = 0.f;
            for (int j = 0; j < HID; ++j) s += h_s[t][j] * w_nfc[k * HID + j];
            l[k] = s * (1.f / 30.f);
            mx = fmaxf(mx, l[k]);
        }
        float den = 0.f;
        for (int k = 0; k < KNUM; ++k) { l[k] = expf(l[k] - mx); den += l[k]; }
        float inv = 1.f / den;
        for (int k = 0; k < KNUM; ++k) natt_s[t][k] = l[k] * inv;
    }
    if (t >= 64 && t < 64 + BS * 9) {
        int idx = t - 64;
        int b = idx / 9, cd = idx % 9;
        float s = 0.f;
        for (int j = 0; j < HID; ++j) s += h_s[b][j] * w_k2[cd * HID + j];
        k2_s[b][cd] = sigmoidf_(s);
    }
    __syncthreads();
    if (t < BS * 9) {
        int b = t / 9, cd = t % 9;
        float m[9];
#pragma unroll
        for (int s = 0; s < 9; ++s) m[s] = 0.f;
#pragma unroll
        for (int k = 0; k < KNUM; ++k) m[c_perm[k][cd]] += natt_s[b][k];
        float k2v = k2_s[b][cd];
#pragma unroll
        for (int s = 0; s < 9; ++s) g_mix[(b * 9 + cd) * 9 + s] = k2v * m[s];
    }
    for (int idx = t; idx < BS * CIN; idx += blockDim.x) {
        int b = idx >> 8, c = idx & 255;
        float s1 = 0.f, s2 = 0.f;
        for (int j = 0; j < HID; ++j) {
            float hv = h_s[b][j];
            s1 += hv * w_cin[c * HID + j];
            s2 += hv * w_out[c * HID + j];
        }
        g_cinatt[idx] = sigmoidf_(s1);
        g_outatt[idx] = sigmoidf_(s2);
        float bb = natt_s[b][0] * b_base[c];
        for (int k = 1; k < KNUM; ++k) bb += natt_s[b][k] * b_extra[(k - 1) * COUT + c];
        g_aggb[idx] = bb;
    }
}

// ---------------- kernel 3: fused weights -> bf16 hi/lo [b][tap][chunk][o][72] ----------------
__global__ void wfuse_kernel(const float* __restrict__ w_base)
{
    const int o = blockIdx.x, b = blockIdx.y, i = threadIdx.x;
    const int chunk = i >> 6, il = i & 63;
    __shared__ float mix_s[81];
    if (i < 81) mix_s[i] = g_mix[b * 81 + i];
    __syncthreads();
    float wb[9];
    const float* wp = &w_base[((size_t)o * CIN + i) * 9];
#pragma unroll
    for (int s = 0; s < 9; ++s) wb[s] = wp[s];
    float sc = g_cinatt[b * CIN + i] * g_outatt[b * COUT + o];
#pragma unroll
    for (int tap = 0; tap < 9; ++tap) {
        float v = 0.f;
#pragma unroll
        for (int s = 0; s < 9; ++s) v += mix_s[tap * 9 + s] * wb[s];
        v *= sc;
        __nv_bfloat16 vh = __float2bfloat16(v);
        float vl = v - __bfloat162float(vh);
        size_t off = ((((size_t)(b * 9 + tap) * 4 + chunk) * COUT + o) * 72) + il;
        g_wh[off] = vh;
        g_wl[off] = __float2bfloat16(vl);
    }
}

// ---------------- kernel 4: x -> padded chunked HWC bf16 hi/lo + fused pool sums ----------------
__global__ void xcvt_kernel(const float* __restrict__ x)
{
    const int rp  = blockIdx.x;               // 0..81 rows, 82/83 slack blocks
    const int b   = blockIdx.y;
    const int tid = threadIdx.x;

    if (rp >= QROW) {                         // zero halo slack (cols 0..63)
        const size_t r0 = (rp == QROW) ? 0 : (size_t)(PADQ + QP);
        for (int idx = tid; idx < 4 * PADQ * 64; idx += 256) {
            int chunk = idx / (PADQ * 64);
            int rem   = idx - chunk * PADQ * 64;
            int r     = rem >> 6, c = rem & 63;
            size_t off = (((size_t)(b * 4 + chunk) * QTOT + r0 + r) * 72) + c;
            g_xh[off] = __float2bfloat16(0.f);
            g_xl[off] = __float2bfloat16(0.f);
        }
        return;
    }

    if (rp == 0 || rp == 81) {                // zero grid border rows
        for (int idx = tid; idx < 4 * QROW * 64; idx += 256) {
            int chunk = idx / (QROW * 64);
            int rem   = idx - chunk * QROW * 64;
            int cp    = rem >> 6, c = rem & 63;
            size_t off = (((size_t)(b * 4 + chunk) * QTOT + PADQ + (size_t)rp * QROW + cp) * 72) + c;
            g_xh[off] = __float2bfloat16(0.f);
            g_xl[off] = __float2bfloat16(0.f);
        }
        return;
    }

    const int h = rp - 1;
    __shared__ float sm[64][81];
    for (int chunk = 0; chunk < 4; ++chunk) {
        const int i0 = chunk * 64;
        for (int k = tid; k < 64 * 80; k += 256) {
            int i = k / 80, w = k % 80;
            sm[i][w] = x[(((size_t)b * CIN + i0 + i) * HH + h) * WW + w];
        }
        __syncthreads();
        // fused pool: per-channel row sums
        if (tid < 64) {
            float s = 0.f;
#pragma unroll 4
            for (int w = 0; w < 80; ++w) s += sm[tid][w];
            atomicAdd(&g_pooled[b * CIN + i0 + tid], s);
        }
        int grp = tid >> 6, il = tid & 63;
        const size_t rbase = ((size_t)(b * 4 + chunk) * QTOT + PADQ + (size_t)rp * QROW) * 72;
        for (int cp = grp; cp < QROW; cp += 4) {
            int w = cp - 1;
            float v = ((unsigned)w < 80u) ? sm[il][w] : 0.f;
            __nv_bfloat16 vh = __float2bfloat16(v);
            float vl = v - __bfloat162float(vh);
            size_t off = rbase + (size_t)cp * 72 + il;
            g_xh[off] = vh;
            g_xl[off] = __float2bfloat16(vl);
        }
        __syncthreads();
    }
}

// ---------------- kernel 5: HMMA split-bf16 conv, RAW-distance-16 MMA schedule ----------------
// grid (26, 2, 16); 544 threads: warps 0-15 compute (4M x 4N, warp tile 32x64),
// warp 16 = producer. No block-wide syncs in the mainloop.
__global__ __launch_bounds__(544, 1)
void conv_mma_kernel(float* __restrict__ out)
{
    extern __shared__ __align__(128) char smem[];
    const uint32_t sb = smem_u32(smem);
    const int tid  = threadIdx.x;
    const int lane = tid & 31;
    const int wid  = tid >> 5;
    const int b    = blockIdx.z;
    const int ocb  = blockIdx.y;
    const int q0   = QROW + blockIdx.x * NTILE;
    const int qbase = q0 - 83;

    const uint32_t mb_wf0 = sb + SO_BAR;
    const uint32_t mb_wf1 = sb + SO_BAR + 8;
    const uint32_t mb_we0 = sb + SO_BAR + 16;
    const uint32_t mb_we1 = sb + SO_BAR + 24;
    const uint32_t mb_xf  = sb + SO_BAR + 32;
    const uint32_t mb_xe  = sb + SO_BAR + 40;

    if (tid == 0) {
        MBARRIER_INIT(mb_wf0, 1);
        MBARRIER_INIT(mb_wf1, 1);
        MBARRIER_INIT(mb_we0, 512);
        MBARRIER_INIT(mb_we1, 512);
        MBARRIER_INIT(mb_xf, 1);
        MBARRIER_INIT(mb_xe, 512);
        FENCE_PROXY_ASYNC();
    }
    __syncthreads();

    if (wid == 16) {                          // ---- producer warp ----
        if (elect_one_pred()) {
            auto issueW = [&](int s) {
                const int tap = s % 9, ch = s / 9, buf = s & 1;
                const uint32_t mb = buf ? mb_wf1 : mb_wf0;
                const size_t base = (((size_t)(b * 9 + tap) * 4 + ch) * COUT
                                     + (size_t)ocb * MTILE) * 72;
                MBARRIER_EXPECT_TX(mb, 2 * W_STAGE_B);
                BULK_G2S(sb + SO_WH(buf), (const char*)g_wh + base * 2, W_STAGE_B, mb);
                BULK_G2S(sb + SO_WL(buf), (const char*)g_wl + base * 2, W_STAGE_B, mb);
            };
            auto issueX = [&](int ch) {
                const size_t base = ((size_t)(b * 4 + ch) * QTOT + PADQ + qbase) * 72;
                MBARRIER_EXPECT_TX(mb_xf, 2 * X_STAGE_B);
                BULK_G2S(sb + SO_XH, (const char*)g_xh + base * 2, X_STAGE_B, mb_xf);
                BULK_G2S(sb + SO_XL, (const char*)g_xl + base * 2, X_STAGE_B, mb_xf);
            };
            issueX(0);
            issueW(0);
            issueW(1);
#pragma unroll 1
            for (int s = 2; s < 36; ++s) {
                if (s % 9 == 0) {
                    const int ch = s / 9;
                    MBARRIER_WAIT_PARITY(mb_xe, (ch - 1) & 1);
                    issueX(ch);
                }
                MBARRIER_WAIT_PARITY(s & 1 ? mb_we1 : mb_we0, ((s >> 1) + 1) & 1);
                issueW(s);
            }
        }
        return;
    }

    // ---- compute warps ----
    const int m0 = (wid >> 2) * 32;
    const int n0 = (wid & 3) * 64;
    const uint32_t aoff = (uint32_t)((lane & 15) * XROWB + (lane >> 4) * 16);

    float d[2][8][4];
#pragma unroll
    for (int mt = 0; mt < 2; ++mt)
#pragma unroll
        for (int nt = 0; nt < 8; ++nt)
#pragma unroll
            for (int e = 0; e < 4; ++e) d[mt][nt][e] = 0.f;

    int s = 0;
#pragma unroll 1
    for (int ch = 0; ch < 4; ++ch) {
        MBARRIER_WAIT_PARITY(mb_xf, ch & 1);

#pragma unroll 1
        for (int tap = 0; tap < 9; ++tap, ++s) {
            const int buf = s & 1;
            MBARRIER_WAIT_PARITY(buf ? mb_wf1 : mb_wf0, (s >> 1) & 1);

            const int dlt = (tap / 3 - 1) * QROW + (tap % 3) - 1;
            const uint32_t xrow = (uint32_t)(n0 + dlt + 83);
            const uint32_t xh_b = sb + SO_XH + xrow * XROWB + aoff;
            const uint32_t xl_b = sb + SO_XL + xrow * XROWB + aoff;
            const uint32_t wh_b = sb + SO_WH(buf) + (uint32_t)m0 * XROWB + aoff;
            const uint32_t wl_b = sb + SO_WL(buf) + (uint32_t)m0 * XROWB + aoff;

#pragma unroll
            for (int kk = 0; kk < 4; ++kk) {
                const uint32_t ko = kk * 32;
                uint32_t ah[2][4], al[2][4], bh[4][4], bl[4][4];
                // hoist ALL fragment loads: LDS latency hidden under pass 1
                LDSM4(ah[0], wh_b + ko);
                LDSM4(ah[1], wh_b + 16 * XROWB + ko);
                LDSM4(al[0], wl_b + ko);
                LDSM4(al[1], wl_b + 16 * XROWB + ko);
#pragma unroll
                for (int j = 0; j < 4; ++j) LDSM4(bh[j], xh_b + j * 16 * XROWB + ko);
#pragma unroll
                for (int j = 0; j < 4; ++j) LDSM4(bl[j], xl_b + j * 16 * XROWB + ko);

                // pass 1: Wh*Xh — 16 MMAs, 16 distinct accumulators
#pragma unroll
                for (int mt = 0; mt < 2; ++mt)
#pragma unroll
                    for (int j = 0; j < 4; ++j) {
                        MMA(d[mt][2 * j],     ah[mt], bh[j][0], bh[j][2]);
                        MMA(d[mt][2 * j + 1], ah[mt], bh[j][1], bh[j][3]);
                    }
                // pass 2: Wl*Xh — RAW distance 16 from pass 1
#pragma unroll
                for (int mt = 0; mt < 2; ++mt)
#pragma unroll
                    for (int j = 0; j < 4; ++j) {
                        MMA(d[mt][2 * j],     al[mt], bh[j][0], bh[j][2]);
                        MMA(d[mt][2 * j + 1], al[mt], bh[j][1], bh[j][3]);
                    }
                // pass 3: Wh*Xl — RAW distance 16 from pass 2
#pragma unroll
                for (int mt = 0; mt < 2; ++mt)
#pragma unroll
                    for (int j = 0; j < 4; ++j) {
                        MMA(d[mt][2 * j],     ah[mt], bl[j][0], bl[j][2]);
                        MMA(d[mt][2 * j + 1], ah[mt], bl[j][1], bl[j][3]);
                    }
            }

            FENCE_PROXY_ASYNC();              // order LDSM reads before async reuse
            MBARRIER_ARRIVE(buf ? mb_we1 : mb_we0);
            if (tap == 8) MBARRIER_ARRIVE(mb_xe);
        }
    }

    // ---- epilogue: predicated stores with bias ----
    const int mbase = ocb * MTILE + m0;
    const int qb = q0 + n0;
#pragma unroll
    for (int mt = 0; mt < 2; ++mt) {
#pragma unroll
        for (int r = 0; r < 2; ++r) {
            const int m = mbase + mt * 16 + (lane >> 2) + r * 8;
            const float bias = g_aggb[b * COUT + m];
            float* ob = out + ((size_t)(b * COUT + m)) * HWSZ;
#pragma unroll
            for (int nt = 0; nt < 8; ++nt) {
                const int q = qb + nt * 8 + (lane & 3) * 2;
#pragma unroll
                for (int e = 0; e < 2; ++e) {
                    const int qq = q + e;
                    const int rq = qq / QROW;
                    const int cq = qq - rq * QROW;
                    if (rq >= 1 && rq <= 80 && cq >= 1 && cq <= 80)
                        ob[(rq - 1) * WW + (cq - 1)] = d[mt][nt][r * 2 + e] + bias;
                }
            }
        }
    }
}

// ---------------- launch ----------------
extern "C" void kernel_launch(void* const* d_in, const int* in_sizes, int n_in,
                              void* d_out, int out_size)
{
    const float* x       = (const float*)d_in[0];
    const float* w_base  = (const float*)d_in[1];
    const float* b_base  = (const float*)d_in[2];
    const float* b_extra = (const float*)d_in[3];
    const float* w_net   = (const float*)d_in[4];
    const float* w_nfc   = (const float*)d_in[5];
    const float* w_cin   = (const float*)d_in[6];
    const float* w_k2    = (const float*)d_in[7];
    const float* w_out   = (const float*)d_in[8];
    float* out = (float*)d_out;

    cudaFuncSetAttribute(conv_mma_kernel,
                         cudaFuncAttributeMaxDynamicSharedMemorySize, SMEM_TOTAL);

    void* ppool = nullptr;
    cudaGetSymbolAddress(&ppool, g_pooled);
    cudaMemsetAsync(ppool, 0, BS * CIN * sizeof(float));

    {
        dim3 grid(QROW + 2, BS);
        xcvt_kernel<<<grid, 256>>>(x);        // also accumulates pool sums
    }
    att_kernel<<<1, 256>>>(w_net, w_nfc, w_cin, w_k2, w_out, b_base, b_extra);
    {
        dim3 grid(COUT, BS);
        wfuse_kernel<<<grid, 256>>>(w_base);
    }
    {
        dim3 grid(NT, 2, BS);
        conv_mma_kernel<<<grid, 544, SMEM_TOTAL>>>(out);
    }
}

// round 15
// speedup vs baseline: 1.0017x; 1.0017x over previous
#include <cuda_runtime.h>
#include <cuda_bf16.h>
#include <math.h>
#include <stdint.h>

#define BS   16
#define CIN  256
#define COUT 256
#define HH   80
#define WW   80
#define HWSZ 6400
#define HID  16
#define KNUM 5

// padded spatial grid: 82x82 (1-halo), row stride 82
#define QROW 82
#define QP   6724
#define PADQ 128                 // slack rows either side (halo over/under-run)
#define QTOT (QP + 2 * PADQ)     // 6980
#define NTILE 256                // GEMM N per CTA
#define NT    26
#define MTILE 128                // GEMM M per CTA
#define SPAN  422                // NTILE + 2*83 halo rows per chunk
#define XROWB 144                // row pitch bytes (72 bf16), gmem AND smem

// smem layout (bytes)
#define SO_XH     0
#define SO_XL     60768                      // SPAN*144
#define SO_WH(bf) (121536 + (bf) * 18432)
#define SO_WL(bf) (158400 + (bf) * 18432)
#define SO_BAR    195264
#define SMEM_TOTAL 195392
#define W_STAGE_B  18432                     // 128*144
#define X_STAGE_B  60768                     // 422*144

// ---------------- scratch ----------------
__device__ float g_pooled[BS * CIN];         // raw sums (memset 0 each call)
__device__ float g_mix[BS * 9 * 9];
__device__ float g_cinatt[BS * CIN];
__device__ float g_outatt[BS * COUT];
__device__ float g_aggb[BS * COUT];

__device__ __align__(128) __nv_bfloat16 g_xh[(size_t)BS * 4 * QTOT * 72];
__device__ __align__(128) __nv_bfloat16 g_xl[(size_t)BS * 4 * QTOT * 72];
__device__ __align__(128) __nv_bfloat16 g_wh[(size_t)BS * 9 * 4 * COUT * 72];
__device__ __align__(128) __nv_bfloat16 g_wl[(size_t)BS * 9 * 4 * COUT * 72];

__constant__ int c_perm[KNUM][9] = {
    {0,1,2,3,4,5,6,7,8},
    {3,0,1,6,4,2,7,8,5},
    {6,3,0,7,4,1,8,5,2},
    {7,6,3,8,4,0,5,2,1},
    {8,7,6,5,4,3,2,1,0},
};

__device__ __forceinline__ float sigmoidf_(float z) { return 1.f / (1.f + expf(-z)); }

// ================= low-level helpers =================
__device__ __forceinline__ uint32_t smem_u32(const void* p)
{
    return (uint32_t)__cvta_generic_to_shared(p);
}
__device__ __forceinline__ uint32_t elect_one_pred()
{
    uint32_t pred;
    asm volatile("{\n\t.reg .pred p;\n\telect.sync _|p, 0xFFFFFFFF;\n\t"
                 "selp.b32 %0, 1, 0, p;\n\t}" : "=r"(pred));
    return pred;
}
#define MBARRIER_INIT(addr, cnt) \
    asm volatile("mbarrier.init.shared.b64 [%0], %1;" :: "r"(addr), "r"(cnt) : "memory")
#define MBARRIER_EXPECT_TX(addr, tx) \
    asm volatile("mbarrier.arrive.expect_tx.shared.b64 _, [%0], %1;" :: "r"(addr), "r"(tx) : "memory")
#define MBARRIER_ARRIVE(addr) \
    asm volatile("mbarrier.arrive.shared.b64 _, [%0];" :: "r"(addr) : "memory")
#define MBARRIER_WAIT_PARITY(addr, par) do {                                        \
    uint32_t _m = (addr), _p = (par);                                               \
    asm volatile("{\n\t.reg .pred P1;\n\t"                                          \
        "WL_%=:\n\t"                                                                \
        "mbarrier.try_wait.parity.acquire.cta.shared::cta.b64 P1, [%0], %1, 0x989680;\n\t" \
        "@P1 bra.uni WD_%=;\n\t"                                                    \
        "bra.uni WL_%=;\n\t"                                                        \
        "WD_%=:\n\t}" :: "r"(_m), "r"(_p) : "memory");                              \
} while (0)
#define BULK_G2S(dst, src, bytes, mbar)                                             \
    asm volatile("cp.async.bulk.shared::cta.global.mbarrier::complete_tx::bytes "   \
        "[%0], [%1], %2, [%3];"                                                     \
        :: "r"((uint32_t)(dst)), "l"(src), "r"((uint32_t)(bytes)),                  \
           "r"((uint32_t)(mbar)) : "memory")
#define FENCE_PROXY_ASYNC() asm volatile("fence.proxy.async.shared::cta;" ::: "memory")

#define LDSM4(r, addr)                                                        \
    asm volatile("ldmatrix.sync.aligned.m8n8.x4.shared.b16 {%0,%1,%2,%3}, [%4];" \
                 : "=r"((r)[0]), "=r"((r)[1]), "=r"((r)[2]), "=r"((r)[3])     \
                 : "r"(addr))

#define MMA(d, a, b0, b1)                                                     \
    asm volatile("mma.sync.aligned.m16n8k16.row.col.f32.bf16.bf16.f32 "      \
                 "{%0,%1,%2,%3}, {%4,%5,%6,%7}, {%8,%9}, {%0,%1,%2,%3};"     \
                 : "+f"((d)[0]), "+f"((d)[1]), "+f"((d)[2]), "+f"((d)[3])    \
                 : "r"((a)[0]), "r"((a)[1]), "r"((a)[2]), "r"((a)[3]),       \
                   "r"(b0), "r"(b1))

// ---------------- kernel 2: attention heads + mix + bias ----------------
__global__ void att_kernel(const float* __restrict__ w_net,
                           const float* __restrict__ w_nfc,
                           const float* __restrict__ w_cin,
                           const float* __restrict__ w_k2,
                           const float* __restrict__ w_out,
                           const float* __restrict__ b_base,
                           const float* __restrict__ b_extra)
{
    __shared__ float h_s[BS][HID];
    __shared__ float natt_s[BS][KNUM];
    __shared__ float k2_s[BS][9];
    int t = threadIdx.x;
    {
        int b = t >> 4, j = t & 15;
        const float* pr = &g_pooled[b * CIN];
        const float* wr = &w_net[j * CIN];
        float s = 0.f;
        for (int i = 0; i < CIN; ++i) s += pr[i] * wr[i];
        h_s[b][j] = fmaxf(s * (1.f / (float)HWSZ), 0.f);   // pooled holds raw sums
    }
    __syncthreads();
    if (t < BS) {
        float l[KNUM];
        float mx = -1e30f;
        for (int k = 0; k < KNUM; ++k) {
            float s = 0.f;
            for (int j = 0; j < HID; ++j) s += h_s[t][j] * w_nfc[k * HID + j];
            l[k] = s * (1.f / 30.f);
            mx = fmaxf(mx, l[k]);
        }
        float den = 0.f;
        for (int k = 0; k < KNUM; ++k) { l[k] = expf(l[k] - mx); den += l[k]; }
        float inv = 1.f / den;
        for (int k = 0; k < KNUM; ++k) natt_s[t][k] = l[k] * inv;
    }
    if (t >= 64 && t < 64 + BS * 9) {
        int idx = t - 64;
        int b = idx / 9, cd = idx % 9;
        float s = 0.f;
        for (int j = 0; j < HID; ++j) s += h_s[b][j] * w_k2[cd * HID + j];
        k2_s[b][cd] = sigmoidf_(s);
    }
    __syncthreads();
    if (t < BS * 9) {
        int b = t / 9, cd = t % 9;
        float m[9];
#pragma unroll
        for (int s = 0; s < 9; ++s) m[s] = 0.f;
#pragma unroll
        for (int k = 0; k < KNUM; ++k) m[c_perm[k][cd]] += natt_s[b][k];
        float k2v = k2_s[b][cd];
#pragma unroll
        for (int s = 0; s < 9; ++s) g_mix[(b * 9 + cd) * 9 + s] = k2v * m[s];
    }
    for (int idx = t; idx < BS * CIN; idx += blockDim.x) {
        int b = idx >> 8, c = idx & 255;
        float s1 = 0.f, s2 = 0.f;
        for (int j = 0; j < HID; ++j) {
            float hv = h_s[b][j];
            s1 += hv * w_cin[c * HID + j];
            s2 += hv * w_out[c * HID + j];
        }
        g_cinatt[idx] = sigmoidf_(s1);
        g_outatt[idx] = sigmoidf_(s2);
        float bb = natt_s[b][0] * b_base[c];
        for (int k = 1; k < KNUM; ++k) bb += natt_s[b][k] * b_extra[(k - 1) * COUT + c];
        g_aggb[idx] = bb;
    }
}

// ---------------- kernel 3: fused weights -> bf16 hi/lo [b][tap][chunk][o][72] ----------------
__global__ void wfuse_kernel(const float* __restrict__ w_base)
{
    const int o = blockIdx.x, b = blockIdx.y, i = threadIdx.x;
    const int chunk = i >> 6, il = i & 63;
    __shared__ float mix_s[81];
    if (i < 81) mix_s[i] = g_mix[b * 81 + i];
    __syncthreads();
    float wb[9];
    const float* wp = &w_base[((size_t)o * CIN + i) * 9];
#pragma unroll
    for (int s = 0; s < 9; ++s) wb[s] = wp[s];
    float sc = g_cinatt[b * CIN + i] * g_outatt[b * COUT + o];
#pragma unroll
    for (int tap = 0; tap < 9; ++tap) {
        float v = 0.f;
#pragma unroll
        for (int s = 0; s < 9; ++s) v += mix_s[tap * 9 + s] * wb[s];
        v *= sc;
        __nv_bfloat16 vh = __float2bfloat16(v);
        float vl = v - __bfloat162float(vh);
        size_t off = ((((size_t)(b * 9 + tap) * 4 + chunk) * COUT + o) * 72) + il;
        g_wh[off] = vh;
        g_wl[off] = __float2bfloat16(vl);
    }
}

// ---------------- kernel 4: x -> padded chunked HWC bf16 hi/lo + fused pool sums ----------------
__global__ void xcvt_kernel(const float* __restrict__ x)
{
    const int rp  = blockIdx.x;               // 0..81 rows, 82/83 slack blocks
    const int b   = blockIdx.y;
    const int tid = threadIdx.x;

    if (rp >= QROW) {                         // zero halo slack (cols 0..63)
        const size_t r0 = (rp == QROW) ? 0 : (size_t)(PADQ + QP);
        for (int idx = tid; idx < 4 * PADQ * 64; idx += 256) {
            int chunk = idx / (PADQ * 64);
            int rem   = idx - chunk * PADQ * 64;
            int r     = rem >> 6, c = rem & 63;
            size_t off = (((size_t)(b * 4 + chunk) * QTOT + r0 + r) * 72) + c;
            g_xh[off] = __float2bfloat16(0.f);
            g_xl[off] = __float2bfloat16(0.f);
        }
        return;
    }

    if (rp == 0 || rp == 81) {                // zero grid border rows
        for (int idx = tid; idx < 4 * QROW * 64; idx += 256) {
            int chunk = idx / (QROW * 64);
            int rem   = idx - chunk * QROW * 64;
            int cp    = rem >> 6, c = rem & 63;
            size_t off = (((size_t)(b * 4 + chunk) * QTOT + PADQ + (size_t)rp * QROW + cp) * 72) + c;
            g_xh[off] = __float2bfloat16(0.f);
            g_xl[off] = __float2bfloat16(0.f);
        }
        return;
    }

    const int h = rp - 1;
    __shared__ float sm[64][81];
    for (int chunk = 0; chunk < 4; ++chunk) {
        const int i0 = chunk * 64;
        for (int k = tid; k < 64 * 80; k += 256) {
            int i = k / 80, w = k % 80;
            sm[i][w] = x[(((size_t)b * CIN + i0 + i) * HH + h) * WW + w];
        }
        __syncthreads();
        // fused pool: per-channel row sums
        if (tid < 64) {
            float s = 0.f;
#pragma unroll 4
            for (int w = 0; w < 80; ++w) s += sm[tid][w];
            atomicAdd(&g_pooled[b * CIN + i0 + tid], s);
        }
        int grp = tid >> 6, il = tid & 63;
        const size_t rbase = ((size_t)(b * 4 + chunk) * QTOT + PADQ + (size_t)rp * QROW) * 72;
        for (int cp = grp; cp < QROW; cp += 4) {
            int w = cp - 1;
            float v = ((unsigned)w < 80u) ? sm[il][w] : 0.f;
            __nv_bfloat16 vh = __float2bfloat16(v);
            float vl = v - __bfloat162float(vh);
            size_t off = rbase + (size_t)cp * 72 + il;
            g_xh[off] = vh;
            g_xl[off] = __float2bfloat16(vl);
        }
        __syncthreads();
    }
}

// ---------------- kernel 5: HMMA split-bf16 conv, RAW-distance-16 MMA schedule ----------------
// grid (26, 2, 16); 544 threads: warps 0-15 compute (4M x 4N, warp tile 32x64),
// warp 16 = producer. No block-wide syncs in the mainloop.
__global__ __launch_bounds__(544, 1)
void conv_mma_kernel(float* __restrict__ out)
{
    extern __shared__ __align__(128) char smem[];
    const uint32_t sb = smem_u32(smem);
    const int tid  = threadIdx.x;
    const int lane = tid & 31;
    const int wid  = tid >> 5;
    const int b    = blockIdx.z;
    const int ocb  = blockIdx.y;
    const int q0   = QROW + blockIdx.x * NTILE;
    const int qbase = q0 - 83;

    const uint32_t mb_wf0 = sb + SO_BAR;
    const uint32_t mb_wf1 = sb + SO_BAR + 8;
    const uint32_t mb_we0 = sb + SO_BAR + 16;
    const uint32_t mb_we1 = sb + SO_BAR + 24;
    const uint32_t mb_xf  = sb + SO_BAR + 32;
    const uint32_t mb_xe  = sb + SO_BAR + 40;

    if (tid == 0) {
        MBARRIER_INIT(mb_wf0, 1);
        MBARRIER_INIT(mb_wf1, 1);
        MBARRIER_INIT(mb_we0, 512);
        MBARRIER_INIT(mb_we1, 512);
        MBARRIER_INIT(mb_xf, 1);
        MBARRIER_INIT(mb_xe, 512);
        FENCE_PROXY_ASYNC();
    }
    __syncthreads();

    if (wid == 16) {                          // ---- producer warp ----
        if (elect_one_pred()) {
            auto issueW = [&](int s) {
                const int tap = s % 9, ch = s / 9, buf = s & 1;
                const uint32_t mb = buf ? mb_wf1 : mb_wf0;
                const size_t base = (((size_t)(b * 9 + tap) * 4 + ch) * COUT
                                     + (size_t)ocb * MTILE) * 72;
                MBARRIER_EXPECT_TX(mb, 2 * W_STAGE_B);
                BULK_G2S(sb + SO_WH(buf), (const char*)g_wh + base * 2, W_STAGE_B, mb);
                BULK_G2S(sb + SO_WL(buf), (const char*)g_wl + base * 2, W_STAGE_B, mb);
            };
            auto issueX = [&](int ch) {
                const size_t base = ((size_t)(b * 4 + ch) * QTOT + PADQ + qbase) * 72;
                MBARRIER_EXPECT_TX(mb_xf, 2 * X_STAGE_B);
                BULK_G2S(sb + SO_XH, (const char*)g_xh + base * 2, X_STAGE_B, mb_xf);
                BULK_G2S(sb + SO_XL, (const char*)g_xl + base * 2, X_STAGE_B, mb_xf);
            };
            issueX(0);
            issueW(0);
            issueW(1);
#pragma unroll 1
            for (int s = 2; s < 36; ++s) {
                if (s % 9 == 0) {
                    const int ch = s / 9;
                    MBARRIER_WAIT_PARITY(mb_xe, (ch - 1) & 1);
                    issueX(ch);
                }
                MBARRIER_WAIT_PARITY(s & 1 ? mb_we1 : mb_we0, ((s >> 1) + 1) & 1);
                issueW(s);
            }
        }
        return;
    }

    // ---- compute warps ----
    const int m0 = (wid >> 2) * 32;
    const int n0 = (wid & 3) * 64;
    const uint32_t aoff = (uint32_t)((lane & 15) * XROWB + (lane >> 4) * 16);

    float d[2][8][4];
#pragma unroll
    for (int mt = 0; mt < 2; ++mt)
#pragma unroll
        for (int nt = 0; nt < 8; ++nt)
#pragma unroll
            for (int e = 0; e < 4; ++e) d[mt][nt][e] = 0.f;

    int s = 0;
#pragma unroll 1
    for (int ch = 0; ch < 4; ++ch) {
        MBARRIER_WAIT_PARITY(mb_xf, ch & 1);

#pragma unroll 1
        for (int tap = 0; tap < 9; ++tap, ++s) {
            const int buf = s & 1;
            MBARRIER_WAIT_PARITY(buf ? mb_wf1 : mb_wf0, (s >> 1) & 1);

            const int dlt = (tap / 3 - 1) * QROW + (tap % 3) - 1;
            const uint32_t xrow = (uint32_t)(n0 + dlt + 83);
            const uint32_t xh_b = sb + SO_XH + xrow * XROWB + aoff;
            const uint32_t xl_b = sb + SO_XL + xrow * XROWB + aoff;
            const uint32_t wh_b = sb + SO_WH(buf) + (uint32_t)m0 * XROWB + aoff;
            const uint32_t wl_b = sb + SO_WL(buf) + (uint32_t)m0 * XROWB + aoff;

#pragma unroll
            for (int kk = 0; kk < 4; ++kk) {
                const uint32_t ko = kk * 32;
                uint32_t ah[2][4], al[2][4], bh[4][4], bl[4][4];
                // hoist ALL fragment loads: LDS latency hidden under pass 1
                LDSM4(ah[0], wh_b + ko);
                LDSM4(ah[1], wh_b + 16 * XROWB + ko);
                LDSM4(al[0], wl_b + ko);
                LDSM4(al[1], wl_b + 16 * XROWB + ko);
#pragma unroll
                for (int j = 0; j < 4; ++j) LDSM4(bh[j], xh_b + j * 16 * XROWB + ko);
#pragma unroll
                for (int j = 0; j < 4; ++j) LDSM4(bl[j], xl_b + j * 16 * XROWB + ko);

                // pass 1: Wh*Xh — 16 MMAs, 16 distinct accumulators
#pragma unroll
                for (int mt = 0; mt < 2; ++mt)
#pragma unroll
                    for (int j = 0; j < 4; ++j) {
                        MMA(d[mt][2 * j],     ah[mt], bh[j][0], bh[j][2]);
                        MMA(d[mt][2 * j + 1], ah[mt], bh[j][1], bh[j][3]);
                    }
                // pass 2: Wl*Xh — RAW distance 16 from pass 1
#pragma unroll
                for (int mt = 0; mt < 2; ++mt)
#pragma unroll
                    for (int j = 0; j < 4; ++j) {
                        MMA(d[mt][2 * j],     al[mt], bh[j][0], bh[j][2]);
                        MMA(d[mt][2 * j + 1], al[mt], bh[j][1], bh[j][3]);
                    }
                // pass 3: Wh*Xl — RAW distance 16 from pass 2
#pragma unroll
                for (int mt = 0; mt < 2; ++mt)
#pragma unroll
                    for (int j = 0; j < 4; ++j) {
                        MMA(d[mt][2 * j],     ah[mt], bl[j][0], bl[j][2]);
                        MMA(d[mt][2 * j + 1], ah[mt], bl[j][1], bl[j][3]);
                    }
            }

            FENCE_PROXY_ASYNC();              // order LDSM reads before async reuse
            MBARRIER_ARRIVE(buf ? mb_we1 : mb_we0);
            if (tap == 8) MBARRIER_ARRIVE(mb_xe);
        }
    }

    // ---- epilogue: predicated stores with bias ----
    const int mbase = ocb * MTILE + m0;
    const int qb = q0 + n0;
#pragma unroll
    for (int mt = 0; mt < 2; ++mt) {
#pragma unroll
        for (int r = 0; r < 2; ++r) {
            const int m = mbase + mt * 16 + (lane >> 2) + r * 8;
            const float bias = g_aggb[b * COUT + m];
            float* ob = out + ((size_t)(b * COUT + m)) * HWSZ;
#pragma unroll
            for (int nt = 0; nt < 8; ++nt) {
                const int q = qb + nt * 8 + (lane & 3) * 2;
#pragma unroll
                for (int e = 0; e < 2; ++e) {
                    const int qq = q + e;
                    const int rq = qq / QROW;
                    const int cq = qq - rq * QROW;
                    if (rq >= 1 && rq <= 80 && cq >= 1 && cq <= 80)
                        ob[(rq - 1) * WW + (cq - 1)] = d[mt][nt][r * 2 + e] + bias;
                }
            }
        }
    }
}

// ---------------- launch ----------------
extern "C" void kernel_launch(void* const* d_in, const int* in_sizes, int n_in,
                              void* d_out, int out_size)
{
    const float* x       = (const float*)d_in[0];
    const float* w_base  = (const float*)d_in[1];
    const float* b_base  = (const float*)d_in[2];
    const float* b_extra = (const float*)d_in[3];
    const float* w_net   = (const float*)d_in[4];
    const float* w_nfc   = (const float*)d_in[5];
    const float* w_cin   = (const float*)d_in[6];
    const float* w_k2    = (const float*)d_in[7];
    const float* w_out   = (const float*)d_in[8];
    float* out = (float*)d_out;

    cudaFuncSetAttribute(conv_mma_kernel,
                         cudaFuncAttributeMaxDynamicSharedMemorySize, SMEM_TOTAL);

    void* ppool = nullptr;
    cudaGetSymbolAddress(&ppool, g_pooled);
    cudaMemsetAsync(ppool, 0, BS * CIN * sizeof(float));

    {
        dim3 grid(QROW + 2, BS);
        xcvt_kernel<<<grid, 256>>>(x);        // also accumulates pool sums
    }
    att_kernel<<<1, 256>>>(w_net, w_nfc, w_cin, w_k2, w_out, b_base, b_extra);
    {
        dim3 grid(COUT, BS);
        wfuse_kernel<<<grid, 256>>>(w_base);
    }
    {
        dim3 grid(NT, 2, BS);
        conv_mma_kernel<<<grid, 544, SMEM_TOTAL>>>(out);
    }
}